// round 2
// baseline (speedup 1.0000x reference)
#include <cuda_runtime.h>
#include <cuda_bf16.h>

// Problem constants
#define BATCH 8
#define CIN 128
#define COUT 128
#define HH 64
#define WW 64
#define HW 4096            // 64*64
#define PLANE 524288       // CIN*HW = 128*4096 (floats per batch, both layouts)
#define NPIX 32768         // BATCH*HW
#define K2 9

// Scratch (device globals: allocation-free per harness rules)
__device__ float g_xT[BATCH * HW * CIN];     // NHWC transpose of x  (16.8 MB)
__device__ float g_off[NPIX * 18];           // offsets, layout [p][18]
__device__ float g_wT[K2 * CIN * COUT];      // w_conv transposed to [tap][i][o]

// ---------------------------------------------------------------------------
// Kernel 1: NCHW -> NHWC transpose of x
// ---------------------------------------------------------------------------
__global__ void dcb_transpose_kernel(const float* __restrict__ x) {
    __shared__ float tile[32][33];
    int b   = blockIdx.z;
    int ci0 = blockIdx.y * 32;
    int p0  = blockIdx.x * 32;
    int tx = threadIdx.x, ty = threadIdx.y;   // 32 x 8
    const float* xb = x + (size_t)b * PLANE;
    #pragma unroll
    for (int k = 0; k < 32; k += 8)
        tile[ty + k][tx] = xb[(ci0 + ty + k) * HW + p0 + tx];
    __syncthreads();
    float* xTb = g_xT + (size_t)b * PLANE;
    #pragma unroll
    for (int k = 0; k < 32; k += 8)
        xTb[(p0 + ty + k) * CIN + ci0 + tx] = tile[tx][ty + k];
}

// ---------------------------------------------------------------------------
// Kernel 2: w_conv [o][i][ky][kx] -> g_wT [tap][i][o]
// ---------------------------------------------------------------------------
__global__ void dcb_wprep_kernel(const float* __restrict__ wc) {
    int m = blockIdx.x * 256 + threadIdx.x;
    if (m < K2 * CIN * COUT) {
        int tap = m / (CIN * COUT);
        int r   = m - tap * (CIN * COUT);
        int i   = r >> 7;
        int o   = r & 127;
        g_wT[m] = wc[o * (CIN * K2) + i * K2 + tap];
    }
}

// ---------------------------------------------------------------------------
// Kernel 3: offset conv. out[p][c] for c in 0..17
// One warp per group of 16 pixels; lanes split CIN into float4 chunks.
// Dynamic smem: w arranged as ws[tap][c][ci] (9*18*128 floats = 82944 B)
// ---------------------------------------------------------------------------
__global__ __launch_bounds__(256) void dcb_offset_kernel(const float* __restrict__ wofs) {
    extern __shared__ float ws[];
    int tid = threadIdx.x;
    for (int idx = tid; idx < 18 * CIN * K2; idx += 256) {
        int c   = idx / (CIN * K2);
        int r   = idx - c * (CIN * K2);
        int ci  = r / K2;
        int tap = r - ci * K2;
        ws[(tap * 18 + c) * CIN + ci] = wofs[idx];
    }
    __syncthreads();

    int lane = tid & 31;
    int warp = tid >> 5;
    int wg = blockIdx.x * 8 + warp;          // 0..2047, 16 pixels each
    const float* __restrict__ xT = g_xT;

    for (int q = 0; q < 16; q++) {
        int p   = wg * 16 + q;
        int b   = p >> 12;
        int pix = p & 4095;
        int y   = pix >> 6;
        int x0  = pix & 63;
        const float* xb = xT + b * PLANE;

        float acc[18];
        #pragma unroll
        for (int c = 0; c < 18; c++) acc[c] = 0.f;

        #pragma unroll
        for (int tap = 0; tap < 9; tap++) {
            int yy = y - 1 + tap / 3;
            int xx = x0 - 1 + tap % 3;
            if (yy < 0 || yy > 63 || xx < 0 || xx > 63) continue;
            float4 xv = *(const float4*)&xb[(yy * 64 + xx) * CIN + lane * 4];
            const float* wt = ws + tap * 18 * CIN + lane * 4;
            #pragma unroll
            for (int c = 0; c < 18; c++) {
                float4 wv = *(const float4*)&wt[c * CIN];
                acc[c] += xv.x * wv.x + xv.y * wv.y + xv.z * wv.z + xv.w * wv.w;
            }
        }
        #pragma unroll
        for (int c = 0; c < 18; c++) {
            #pragma unroll
            for (int s = 16; s > 0; s >>= 1)
                acc[c] += __shfl_xor_sync(0xffffffffu, acc[c], s);
        }
        if (lane < 18) {
            float v = 0.f;
            #pragma unroll
            for (int c = 0; c < 18; c++) if (lane == c) v = acc[c];
            g_off[p * 18 + lane] = v;
        }
    }
}

// ---------------------------------------------------------------------------
// Kernel 4: deformable gather + GEMM.
// Block: 512 threads, tile = 128 pixels x 128 couts, K-loop = 9 taps x 128 cin.
// Per tap: compute bilinear meta (128 threads), stage W_k (64KB) + gather
// v tile (64KB) into smem, then f32x2-packed FFMA GEMM.
// Dynamic smem = 135168 B.
// ---------------------------------------------------------------------------
__global__ __launch_bounds__(512, 1) void dcb_deform_kernel(float* __restrict__ out) {
    extern __shared__ float sm[];
    float* v_s   = sm;                       // [128 px][128 i]
    float* w_s   = sm + 16384;               // [128 i][128 o]
    int*   m_idx = (int*)(sm + 32768);       // [128 px][4]
    float* m_w   = sm + 32768 + 512;         // [128 px][4]

    int tid  = threadIdx.x;
    int p0   = blockIdx.x * 128;
    int b    = p0 >> 12;
    int bbase = b << 19;                     // b * PLANE
    int pix0 = p0 & 4095;
    const float* __restrict__ xb = g_xT + bbase;
    const float* __restrict__ offS = g_off;
    const float* __restrict__ wT = g_wT;

    int oc = tid & 31;                       // cout pairs: (2oc,2oc+1),(2oc+64,2oc+65)
    int pc = tid >> 5;                       // pixel group 0..15 -> pixels pc*8..pc*8+7

    unsigned long long acc01[8], acc23[8];
    #pragma unroll
    for (int j = 0; j < 8; j++) { acc01[j] = 0ull; acc23[j] = 0ull; }

    for (int tap = 0; tap < 9; tap++) {
        // ---- phase 1: bilinear metadata ----
        if (tid < 128) {
            int j   = tid;
            int p   = p0 + j;
            int pix = pix0 + j;
            int y   = pix >> 6;
            int xx  = pix & 63;
            float dy = offS[p * 18 + tap * 2];
            float dx = offS[p * 18 + tap * 2 + 1];
            float py = (float)(y - 1 + tap / 3) + dy;
            float px = (float)(xx - 1 + tap % 3) + dx;
            float y0f = floorf(py), x0f = floorf(px);
            float fy = py - y0f, fx = px - x0f;
            float vy0 = (y0f >= 0.f  && y0f <= 63.f) ? 1.f : 0.f;
            float vy1 = (y0f >= -1.f && y0f <= 62.f) ? 1.f : 0.f;
            float vx0 = (x0f >= 0.f  && x0f <= 63.f) ? 1.f : 0.f;
            float vx1 = (x0f >= -1.f && x0f <= 62.f) ? 1.f : 0.f;
            int yi0 = (int)fminf(fmaxf(y0f,        0.f), 63.f);
            int yi1 = (int)fminf(fmaxf(y0f + 1.f,  0.f), 63.f);
            int xi0 = (int)fminf(fmaxf(x0f,        0.f), 63.f);
            int xi1 = (int)fminf(fmaxf(x0f + 1.f,  0.f), 63.f);
            m_idx[j * 4 + 0] = (yi0 * 64 + xi0) << 7;
            m_idx[j * 4 + 1] = (yi0 * 64 + xi1) << 7;
            m_idx[j * 4 + 2] = (yi1 * 64 + xi0) << 7;
            m_idx[j * 4 + 3] = (yi1 * 64 + xi1) << 7;
            m_w[j * 4 + 0] = (1.f - fy) * (1.f - fx) * vy0 * vx0;
            m_w[j * 4 + 1] = (1.f - fy) * fx         * vy0 * vx1;
            m_w[j * 4 + 2] = fy         * (1.f - fx) * vy1 * vx0;
            m_w[j * 4 + 3] = fy         * fx         * vy1 * vx1;
        }
        __syncthreads();

        // ---- phase 2: stage W_k + gather v tile ----
        {
            const float4* src = (const float4*)(wT + tap * (CIN * COUT));
            float4* dst = (float4*)w_s;
            #pragma unroll
            for (int t = 0; t < 8; t++) dst[tid + t * 512] = src[tid + t * 512];
        }
        {
            int ci4 = (tid & 31) * 4;
            int j0  = tid >> 5;
            #pragma unroll
            for (int jj = 0; jj < 8; jj++) {
                int j = j0 + jj * 16;
                int i0 = m_idx[j * 4 + 0], i1 = m_idx[j * 4 + 1];
                int i2 = m_idx[j * 4 + 2], i3 = m_idx[j * 4 + 3];
                float w0 = m_w[j * 4 + 0], w1 = m_w[j * 4 + 1];
                float w2 = m_w[j * 4 + 2], w3 = m_w[j * 4 + 3];
                float4 c0 = *(const float4*)&xb[i0 + ci4];
                float4 c1 = *(const float4*)&xb[i1 + ci4];
                float4 c2 = *(const float4*)&xb[i2 + ci4];
                float4 c3 = *(const float4*)&xb[i3 + ci4];
                float4 v;
                v.x = w0 * c0.x + w1 * c1.x + w2 * c2.x + w3 * c3.x;
                v.y = w0 * c0.y + w1 * c1.y + w2 * c2.y + w3 * c3.y;
                v.z = w0 * c0.z + w1 * c1.z + w2 * c2.z + w3 * c3.z;
                v.w = w0 * c0.w + w1 * c1.w + w2 * c2.w + w3 * c3.w;
                *(float4*)&v_s[j * 128 + ci4] = v;
            }
        }
        __syncthreads();

        // ---- phase 3: GEMM with packed f32x2 FFMA ----
        {
            const float* va = v_s + pc * 8 * 128;
            #pragma unroll 8
            for (int i = 0; i < 128; i++) {
                unsigned long long b0 = ((const unsigned long long*)(w_s + i * 128))[oc];
                unsigned long long b1 = ((const unsigned long long*)(w_s + i * 128))[oc + 32];
                #pragma unroll
                for (int j = 0; j < 8; j++) {
                    float a = va[j * 128 + i];
                    unsigned long long a2;
                    asm("mov.b64 %0, {%1, %1};" : "=l"(a2) : "f"(a));
                    asm("fma.rn.f32x2 %0, %1, %2, %0;" : "+l"(acc01[j]) : "l"(a2), "l"(b0));
                    asm("fma.rn.f32x2 %0, %1, %2, %0;" : "+l"(acc23[j]) : "l"(a2), "l"(b1));
                }
            }
        }
        __syncthreads();
    }

    // ---- epilogue: smem transpose -> coalesced NCHW stores ----
    float* out_s = sm;                       // [128 px][130] padded
    #pragma unroll
    for (int j = 0; j < 8; j++) {
        int px = pc * 8 + j;
        ((unsigned long long*)(out_s + px * 130))[oc]      = acc01[j];
        ((unsigned long long*)(out_s + px * 130 + 64))[oc] = acc23[j];
    }
    __syncthreads();
    float* ob = out + bbase + pix0;
    for (int idx = tid; idx < 16384; idx += 512) {
        int o = idx >> 7;
        int j = idx & 127;
        ob[o * HW + j] = out_s[j * 130 + o];
    }
}

// ---------------------------------------------------------------------------
extern "C" void kernel_launch(void* const* d_in, const int* in_sizes, int n_in,
                              void* d_out, int out_size) {
    const float* x = nullptr;
    const float* wofs = nullptr;
    const float* wconv = nullptr;
    for (int i = 0; i < n_in; i++) {
        if      (in_sizes[i] == BATCH * CIN * HW) x     = (const float*)d_in[i];
        else if (in_sizes[i] == 18 * CIN * K2)    wofs  = (const float*)d_in[i];
        else if (in_sizes[i] == COUT * CIN * K2)  wconv = (const float*)d_in[i];
    }
    float* out = (float*)d_out;

    cudaFuncSetAttribute(dcb_offset_kernel,
                         cudaFuncAttributeMaxDynamicSharedMemorySize, 82944);
    cudaFuncSetAttribute(dcb_deform_kernel,
                         cudaFuncAttributeMaxDynamicSharedMemorySize, 135168);

    dim3 tb(32, 8);
    dim3 tg(HW / 32, CIN / 32, BATCH);
    dcb_transpose_kernel<<<tg, tb>>>(x);

    dcb_wprep_kernel<<<(K2 * CIN * COUT + 255) / 256, 256>>>(wconv);

    dcb_offset_kernel<<<256, 256, 82944>>>(wofs);

    dcb_deform_kernel<<<NPIX / 128, 512, 135168>>>(out);
}